// round 10
// baseline (speedup 1.0000x reference)
#include <cuda_runtime.h>
#include <cuda_fp16.h>
#include <cstdint>

namespace {
constexpr int THREADS = 512;
constexpr int CTAS_PER_G = 37;                // 8*37 = 296 = 2 CTAs x 148 SMs
constexpr int TILES_PER_G = 128;              // 16384 positions / 128

// SMEM byte layout
constexpr int SM_X = 0;                       // X: 128 pos x 64 f16 (128B rows, SW128) = 16KB
constexpr int SM_W = 16384;                   // W^T: 512 n x 64 f16 (128B rows, SW128) = 64KB
constexpr int SMEM_TOTAL = 81920;             // -> 2 CTAs/SM

__device__ __forceinline__ uint32_t smem_u32(const void* p) {
    uint32_t a;
    asm("{ .reg .u64 t; cvta.to.shared.u64 t, %1; cvt.u32.u64 %0, t; }" : "=r"(a) : "l"(p));
    return a;
}
__device__ __forceinline__ uint32_t sw128(uint32_t b) { return b ^ ((b >> 3) & 0x70); }

__device__ __forceinline__ void ldsm_x4(uint32_t& r0, uint32_t& r1, uint32_t& r2,
                                        uint32_t& r3, uint32_t addr) {
    asm volatile("ldmatrix.sync.aligned.m8n8.x4.shared.b16 {%0,%1,%2,%3}, [%4];"
                 : "=r"(r0), "=r"(r1), "=r"(r2), "=r"(r3) : "r"(addr));
}
__device__ __forceinline__ void mma16816(float& d0, float& d1, float& d2, float& d3,
                                         uint32_t a0, uint32_t a1, uint32_t a2, uint32_t a3,
                                         uint32_t b0, uint32_t b1) {
    asm volatile(
        "mma.sync.aligned.m16n8k16.row.col.f32.f16.f16.f32 "
        "{%0,%1,%2,%3}, {%4,%5,%6,%7}, {%8,%9}, {%0,%1,%2,%3};"
        : "+f"(d0), "+f"(d1), "+f"(d2), "+f"(d3)
        : "r"(a0), "r"(a1), "r"(a2), "r"(a3), "r"(b0), "r"(b1));
}

__global__ void __launch_bounds__(THREADS, 2)
deconv_hmma_kernel(const int* __restrict__ indp, const int* __restrict__ indn,
                   const float* __restrict__ valp, const float* __restrict__ valn,
                   const float* __restrict__ wgt, float* __restrict__ out)
{
    extern __shared__ char smc[];
    const uint32_t sb = smem_u32(smc);

    const int tid  = threadIdx.x;
    const int lane = tid & 31;
    const int wp   = tid >> 5;

    const int g    = blockIdx.x / CTAS_PER_G;
    const int cidx = blockIdx.x % CTAS_PER_G;

    // ---- Build W^T in smem: Wsm[n][c] = (f16) wgt[g*32768 + c*512 + n], SW128 rows.
    {
        const int n = tid;                     // 0..511
        #pragma unroll
        for (int c8 = 0; c8 < 8; c8++) {
            const int c0 = c8 * 8;
            unsigned pk[4];
            #pragma unroll
            for (int q = 0; q < 4; q++) {
                float f0 = __ldg(wgt + (size_t)g * 32768 + (size_t)(c0 + 2*q    ) * 512 + n);
                float f1 = __ldg(wgt + (size_t)g * 32768 + (size_t)(c0 + 2*q + 1) * 512 + n);
                __half2 h = __floats2half2_rn(f0, f1);
                pk[q] = *reinterpret_cast<unsigned*>(&h);
            }
            *reinterpret_cast<uint4*>(smc + SM_W + sw128((uint32_t)n * 128 + c0 * 2)) =
                make_uint4(pk[0], pk[1], pk[2], pk[3]);
        }
    }
    __syncthreads();

    // ---- B fragments for this warp's two features: tile-invariant, kernel-lifetime regs.
    const int nr = lane & 7;                   // B ldmatrix row within n8
    const int jm = lane >> 3;                  // B ldmatrix matrix index 0..3
    uint32_t Bf[2][4][4];                      // [feat][k-chunk][frag]
    #pragma unroll
    for (int ft = 0; ft < 2; ft++) {
        const int f = 2 * wp + ft;
        const int nrow = f * 16 + (jm >> 1) * 8 + nr;
        const int kb   = (jm & 1) * 16;
        #pragma unroll
        for (int kc = 0; kc < 4; kc++)
            ldsm_x4(Bf[ft][kc][0], Bf[ft][kc][1], Bf[ft][kc][2], Bf[ft][kc][3],
                    sb + SM_W + sw128((uint32_t)nrow * 128 + kc * 32 + kb));
    }

    const int KS = 32768;                      // k-stride in scatter tensors
    const int r  = lane >> 2;                  // D-frag row within m8
    const int q  = lane & 3;                   // D-frag col pair
    const int i0 = q >> 1;                     // kernel row (tile0)
    const int j0 = (q & 1) * 2;                // kernel col base

    for (int t = cidx; t < TILES_PER_G; t += CTAS_PER_G) {
        const int bb = t >> 5;                 // batch
        const int w0 = (t & 31) * 2;           // first of two w-rows in this tile

        __syncthreads();                       // all A reads of previous X done

        // ---- Build X tile: 128 pos x 64 ch fp16, SW128, program-ordered scatter.
        if (tid < 128) {
            const int pp = tid;
            const int h  = pp & 63;
            const int w  = w0 + (pp >> 6);
            char* xrow = smc + SM_X + pp * 128;
            const uint4 z = make_uint4(0, 0, 0, 0);
            #pragma unroll
            for (int z4 = 0; z4 < 8; z4++)
                *reinterpret_cast<uint4*>(xrow + z4 * 16) = z;
            const int base = (((bb * 4) * 8 + g) << 12) + w * 64 + h;
            const uint32_t rsw = ((uint32_t)pp & 7) << 4;
            #pragma unroll
            for (int k = 0; k < 4; k++) {      // pos scatter (k ascending)
                const int    c = __ldg(indp + base + k * KS);
                const __half v = __float2half(__ldg(valp + base + k * KS));
                *reinterpret_cast<__half*>(xrow + (((uint32_t)(2 * c)) ^ rsw)) = v;
            }
            #pragma unroll
            for (int k = 0; k < 4; k++) {      // neg scatter overwrites pos
                const int    c = __ldg(indn + base + k * KS);
                const __half v = __float2half(__ldg(valn + base + k * KS));
                *reinterpret_cast<__half*>(xrow + (((uint32_t)(2 * c)) ^ rsw)) = v;
            }
        }
        __syncthreads();

        #pragma unroll 1
        for (int s = 0; s < 8; s++) {
            // ---- A fragments: m16k64 for stripe s.
            uint32_t a[4][4];
            {
                const int arow = 16 * s + (lane & 15);
                const int acol = (lane >> 4) * 16;
                #pragma unroll
                for (int kc = 0; kc < 4; kc++)
                    ldsm_x4(a[kc][0], a[kc][1], a[kc][2], a[kc][3],
                            sb + SM_X + sw128((uint32_t)arow * 128 + kc * 32 + acol));
            }

            const int wo = w0 + (s >> 2);
            const int h0 = 16 * (s & 3);

            #pragma unroll
            for (int ft = 0; ft < 2; ft++) {
                float d0 = 0.f, d1 = 0.f, d2 = 0.f, d3 = 0.f;   // n8 tile0: taps 0..7
                float d4 = 0.f, d5 = 0.f, d6 = 0.f, d7 = 0.f;   // n8 tile1: taps 8..15
                #pragma unroll
                for (int kc = 0; kc < 4; kc++) {
                    mma16816(d0, d1, d2, d3, a[kc][0], a[kc][1], a[kc][2], a[kc][3],
                             Bf[ft][kc][0], Bf[ft][kc][1]);
                    mma16816(d4, d5, d6, d7, a[kc][0], a[kc][1], a[kc][2], a[kc][3],
                             Bf[ft][kc][2], Bf[ft][kc][3]);
                }

                // ---- Direct fragment store: 4x STG.64, each covering 2 full 128B lines.
                // addr(i, hh, j) = obase + i*256 + 4*hh + j  (floats)
                const int f = 2 * wp + ft;
                float* obase = out + (((size_t)(bb * 256 + g * 32 + f)) * 256
                                      + 4 * wo) * 256 + 4 * h0;
                float* p = obase + i0 * 256 + 4 * r + j0;
                *reinterpret_cast<float2*>(p)              = make_float2(d0, d1);  // hh=r
                *reinterpret_cast<float2*>(p + 32)         = make_float2(d2, d3);  // hh=r+8
                *reinterpret_cast<float2*>(p + 512)        = make_float2(d4, d5);  // i+2, hh=r
                *reinterpret_cast<float2*>(p + 544)        = make_float2(d6, d7);  // i+2, hh=r+8
            }
        }
    }
}
}  // namespace

extern "C" void kernel_launch(void* const* d_in, const int* in_sizes, int n_in,
                              void* d_out, int out_size) {
    const int*   indp = (const int*)d_in[0];
    const int*   indn = (const int*)d_in[1];
    const float* valp = (const float*)d_in[2];
    const float* valn = (const float*)d_in[3];
    const float* wgt  = (const float*)d_in[4];
    float* out = (float*)d_out;

    cudaFuncSetAttribute(deconv_hmma_kernel,
                         cudaFuncAttributeMaxDynamicSharedMemorySize, SMEM_TOTAL);
    cudaFuncSetAttribute(deconv_hmma_kernel,
                         cudaFuncAttributePreferredSharedMemoryCarveout, 100);
    deconv_hmma_kernel<<<8 * CTAS_PER_G, THREADS, SMEM_TOTAL>>>(
        indp, indn, valp, valn, wgt, out);
}

// round 11
// speedup vs baseline: 1.1159x; 1.1159x over previous
#include <cuda_runtime.h>
#include <cuda_fp16.h>
#include <cstdint>

namespace {
constexpr int THREADS = 512;
constexpr int CTAS_PER_G = 37;                // 8*37 = 296 = 2 CTAs x 148 SMs
constexpr int TILES_PER_G = 128;              // 16384 positions / 128

// SMEM byte layout
constexpr int SM_X = 0;                       // X: 128 pos x 64 f16 (128B rows, SW128) = 16KB
constexpr int SM_W = 16384;                   // W^T: 512 n x 64 f16 (128B rows, SW128) = 64KB
constexpr int SMEM_TOTAL = 81920;             // -> 2 CTAs/SM

__device__ __forceinline__ uint32_t smem_u32(const void* p) {
    uint32_t a;
    asm("{ .reg .u64 t; cvta.to.shared.u64 t, %1; cvt.u32.u64 %0, t; }" : "=r"(a) : "l"(p));
    return a;
}
__device__ __forceinline__ uint32_t sw128(uint32_t b) { return b ^ ((b >> 3) & 0x70); }

__device__ __forceinline__ void ldsm_x4(uint32_t& r0, uint32_t& r1, uint32_t& r2,
                                        uint32_t& r3, uint32_t addr) {
    asm volatile("ldmatrix.sync.aligned.m8n8.x4.shared.b16 {%0,%1,%2,%3}, [%4];"
                 : "=r"(r0), "=r"(r1), "=r"(r2), "=r"(r3) : "r"(addr));
}
__device__ __forceinline__ void mma16816(float& d0, float& d1, float& d2, float& d3,
                                         uint32_t a0, uint32_t a1, uint32_t a2, uint32_t a3,
                                         uint32_t b0, uint32_t b1) {
    asm volatile(
        "mma.sync.aligned.m16n8k16.row.col.f32.f16.f16.f32 "
        "{%0,%1,%2,%3}, {%4,%5,%6,%7}, {%8,%9}, {%0,%1,%2,%3};"
        : "+f"(d0), "+f"(d1), "+f"(d2), "+f"(d3)
        : "r"(a0), "r"(a1), "r"(a2), "r"(a3), "r"(b0), "r"(b1));
}

__global__ void __launch_bounds__(THREADS, 2)
deconv_hmma_kernel(const int* __restrict__ indp, const int* __restrict__ indn,
                   const float* __restrict__ valp, const float* __restrict__ valn,
                   const float* __restrict__ wgt, float* __restrict__ out)
{
    extern __shared__ char smc[];
    const uint32_t sb = smem_u32(smc);

    const int tid  = threadIdx.x;
    const int lane = tid & 31;
    const int wp   = tid >> 5;

    const int g    = blockIdx.x / CTAS_PER_G;
    const int cidx = blockIdx.x % CTAS_PER_G;

    // ---- Build W^T in smem: Wsm[n][c] = (f16) wgt[g*32768 + c*512 + n], SW128 rows.
    {
        const int n = tid;                     // 0..511
        #pragma unroll
        for (int c8 = 0; c8 < 8; c8++) {
            const int c0 = c8 * 8;
            unsigned pk[4];
            #pragma unroll
            for (int q4 = 0; q4 < 4; q4++) {
                float f0 = __ldg(wgt + (size_t)g * 32768 + (size_t)(c0 + 2*q4    ) * 512 + n);
                float f1 = __ldg(wgt + (size_t)g * 32768 + (size_t)(c0 + 2*q4 + 1) * 512 + n);
                __half2 h = __floats2half2_rn(f0, f1);
                pk[q4] = *reinterpret_cast<unsigned*>(&h);
            }
            *reinterpret_cast<uint4*>(smc + SM_W + sw128((uint32_t)n * 128 + c0 * 2)) =
                make_uint4(pk[0], pk[1], pk[2], pk[3]);
        }
    }

    const int KS = 32768;                      // k-stride in scatter tensors
    const int nr = lane & 7;                   // B ldmatrix row within n8
    const int jm = lane >> 3;                  // B ldmatrix matrix index 0..3
    const int r  = lane >> 2;                  // D-frag row within m8
    const int q  = lane & 3;                   // D-frag col pair
    const int e  = q & 1;                      // 0: j={0,1} holder, 1: j={2,3}
    const int ii = q >> 1;                     // kernel row within n8 tile

    for (int t = cidx; t < TILES_PER_G; t += CTAS_PER_G) {
        const int bb = t >> 5;                 // batch
        const int w0 = (t & 31) * 2;           // first of two w-rows in this tile

        __syncthreads();                       // all A reads of previous X done

        // ---- Build X tile: 128 pos x 64 ch fp16, SW128, program-ordered scatter.
        if (tid < 128) {
            const int pp = tid;
            const int h  = pp & 63;
            const int w  = w0 + (pp >> 6);
            char* xrow = smc + SM_X + pp * 128;
            const uint4 z = make_uint4(0, 0, 0, 0);
            #pragma unroll
            for (int z4 = 0; z4 < 8; z4++)
                *reinterpret_cast<uint4*>(xrow + z4 * 16) = z;
            const int base = (((bb * 4) * 8 + g) << 12) + w * 64 + h;
            const uint32_t rsw = ((uint32_t)pp & 7) << 4;
            #pragma unroll
            for (int k = 0; k < 4; k++) {      // pos scatter (k ascending)
                const int    c = __ldg(indp + base + k * KS);
                const __half v = __float2half(__ldg(valp + base + k * KS));
                *reinterpret_cast<__half*>(xrow + (((uint32_t)(2 * c)) ^ rsw)) = v;
            }
            #pragma unroll
            for (int k = 0; k < 4; k++) {      // neg scatter overwrites pos
                const int    c = __ldg(indn + base + k * KS);
                const __half v = __float2half(__ldg(valn + base + k * KS));
                *reinterpret_cast<__half*>(xrow + (((uint32_t)(2 * c)) ^ rsw)) = v;
            }
        }
        __syncthreads();

        #pragma unroll 1
        for (int ft = 0; ft < 2; ft++) {
            const int f = 2 * wp + ft;

            // ---- B fragments for feature f (16 regs, live for this ft pass only).
            uint32_t Bf[4][4];
            {
                const int nrow = f * 16 + (jm >> 1) * 8 + nr;
                const int kb   = (jm & 1) * 16;
                #pragma unroll
                for (int kc = 0; kc < 4; kc++)
                    ldsm_x4(Bf[kc][0], Bf[kc][1], Bf[kc][2], Bf[kc][3],
                            sb + SM_W + sw128((uint32_t)nrow * 128 + kc * 32 + kb));
            }

            #pragma unroll 1
            for (int s = 0; s < 8; s++) {
                // ---- A fragments: m16k64 for stripe s.
                uint32_t a[4][4];
                {
                    const int arow = 16 * s + (lane & 15);
                    const int acol = (lane >> 4) * 16;
                    #pragma unroll
                    for (int kc = 0; kc < 4; kc++)
                        ldsm_x4(a[kc][0], a[kc][1], a[kc][2], a[kc][3],
                                sb + SM_X + sw128((uint32_t)arow * 128 + kc * 32 + acol));
                }

                float d0 = 0.f, d1 = 0.f, d2 = 0.f, d3 = 0.f;   // taps 0..7  (i 0,1)
                float d4 = 0.f, d5 = 0.f, d6 = 0.f, d7 = 0.f;   // taps 8..15 (i 2,3)
                #pragma unroll
                for (int kc = 0; kc < 4; kc++) {
                    mma16816(d0, d1, d2, d3, a[kc][0], a[kc][1], a[kc][2], a[kc][3],
                             Bf[kc][0], Bf[kc][1]);
                    mma16816(d4, d5, d6, d7, a[kc][0], a[kc][1], a[kc][2], a[kc][3],
                             Bf[kc][2], Bf[kc][3]);
                }

                // ---- Shuffle epilogue: lane pair (q, q^1) assembles along-j float4s.
                const int wo = w0 + (s >> 2);
                const int h0 = 16 * (s & 3);
                float* obase = out + (((size_t)(bb * 256 + g * 32 + f)) * 256
                                      + 4 * wo) * 256 + 4 * h0;
                const int hh = r + 8 * e;

                {   // n8 tile 0: kernel rows i = ii
                    float sx = e ? d0 : d2;
                    float sy = e ? d1 : d3;
                    float rx = __shfl_xor_sync(0xFFFFFFFFu, sx, 1);
                    float ry = __shfl_xor_sync(0xFFFFFFFFu, sy, 1);
                    float4 v = e ? make_float4(rx, ry, d2, d3)
                                 : make_float4(d0, d1, rx, ry);
                    *reinterpret_cast<float4*>(obase + (size_t)ii * 256 + 4 * hh) = v;
                }
                {   // n8 tile 1: kernel rows i = 2 + ii
                    float sx = e ? d4 : d6;
                    float sy = e ? d5 : d7;
                    float rx = __shfl_xor_sync(0xFFFFFFFFu, sx, 1);
                    float ry = __shfl_xor_sync(0xFFFFFFFFu, sy, 1);
                    float4 v = e ? make_float4(rx, ry, d6, d7)
                                 : make_float4(d4, d5, rx, ry);
                    *reinterpret_cast<float4*>(obase + (size_t)(2 + ii) * 256 + 4 * hh) = v;
                }
            }
        }
    }
}
}  // namespace

extern "C" void kernel_launch(void* const* d_in, const int* in_sizes, int n_in,
                              void* d_out, int out_size) {
    const int*   indp = (const int*)d_in[0];
    const int*   indn = (const int*)d_in[1];
    const float* valp = (const float*)d_in[2];
    const float* valn = (const float*)d_in[3];
    const float* wgt  = (const float*)d_in[4];
    float* out = (float*)d_out;

    cudaFuncSetAttribute(deconv_hmma_kernel,
                         cudaFuncAttributeMaxDynamicSharedMemorySize, SMEM_TOTAL);
    cudaFuncSetAttribute(deconv_hmma_kernel,
                         cudaFuncAttributePreferredSharedMemoryCarveout, 100);
    deconv_hmma_kernel<<<8 * CTAS_PER_G, THREADS, SMEM_TOTAL>>>(
        indp, indn, valp, valn, wgt, out);
}

// round 13
// speedup vs baseline: 1.2116x; 1.0858x over previous
#include <cuda_runtime.h>
#include <cuda_fp16.h>
#include <cstdint>

namespace {
constexpr int THREADS = 512;
constexpr int CTAS_PER_G = 37;                // 8*37 = 296 = 2 CTAs x 148 SMs
constexpr int TILES_PER_G = 128;              // 16384 positions / 128

// SMEM byte layout
constexpr int SM_X = 0;                       // X: 128 pos x 64 f16 (128B rows, SW128) = 16KB
constexpr int SM_W = 16384;                   // W^T: 512 n x 64 f16 (128B rows, SW128) = 64KB
constexpr int SMEM_TOTAL = 81920;             // -> 2 CTAs/SM

__device__ __forceinline__ uint32_t smem_u32(const void* p) {
    uint32_t a;
    asm("{ .reg .u64 t; cvta.to.shared.u64 t, %1; cvt.u32.u64 %0, t; }" : "=r"(a) : "l"(p));
    return a;
}
__device__ __forceinline__ uint32_t sw128(uint32_t b) { return b ^ ((b >> 3) & 0x70); }

__device__ __forceinline__ void ldsm_x4(uint32_t& r0, uint32_t& r1, uint32_t& r2,
                                        uint32_t& r3, uint32_t addr) {
    asm volatile("ldmatrix.sync.aligned.m8n8.x4.shared.b16 {%0,%1,%2,%3}, [%4];"
                 : "=r"(r0), "=r"(r1), "=r"(r2), "=r"(r3) : "r"(addr));
}
__device__ __forceinline__ void mma16816(float& d0, float& d1, float& d2, float& d3,
                                         uint32_t a0, uint32_t a1, uint32_t a2, uint32_t a3,
                                         uint32_t b0, uint32_t b1) {
    asm volatile(
        "mma.sync.aligned.m16n8k16.row.col.f32.f16.f16.f32 "
        "{%0,%1,%2,%3}, {%4,%5,%6,%7}, {%8,%9}, {%0,%1,%2,%3};"
        : "+f"(d0), "+f"(d1), "+f"(d2), "+f"(d3)
        : "r"(a0), "r"(a1), "r"(a2), "r"(a3), "r"(b0), "r"(b1));
}

__global__ void __launch_bounds__(THREADS, 2)
deconv_hmma_kernel(const int* __restrict__ indp, const int* __restrict__ indn,
                   const float* __restrict__ valp, const float* __restrict__ valn,
                   const float* __restrict__ wgt, float* __restrict__ out)
{
    extern __shared__ char smc[];
    const uint32_t sb = smem_u32(smc);

    const int tid  = threadIdx.x;
    const int lane = tid & 31;
    const int wp   = tid >> 5;

    const int g    = blockIdx.x / CTAS_PER_G;
    const int cidx = blockIdx.x % CTAS_PER_G;

    // ---- Build W^T in smem: Wsm[n][c] = (f16) wgt[g*32768 + c*512 + n], SW128 rows.
    {
        const int n = tid;                     // 0..511
        #pragma unroll
        for (int c8 = 0; c8 < 8; c8++) {
            const int c0 = c8 * 8;
            unsigned pk[4];
            #pragma unroll
            for (int q4 = 0; q4 < 4; q4++) {
                float f0 = __ldg(wgt + (size_t)g * 32768 + (size_t)(c0 + 2*q4    ) * 512 + n);
                float f1 = __ldg(wgt + (size_t)g * 32768 + (size_t)(c0 + 2*q4 + 1) * 512 + n);
                __half2 h = __floats2half2_rn(f0, f1);
                pk[q4] = *reinterpret_cast<unsigned*>(&h);
            }
            *reinterpret_cast<uint4*>(smc + SM_W + sw128((uint32_t)n * 128 + c0 * 2)) =
                make_uint4(pk[0], pk[1], pk[2], pk[3]);
        }
    }
    __syncthreads();

    // ---- B fragments for this warp's two features: loaded ONCE, kernel-lifetime.
    uint32_t Bf[2][4][4];                      // [feat][k-chunk][frag]  (32 regs)
    {
        const int nr = lane & 7;
        const int jm = lane >> 3;
        #pragma unroll
        for (int ft = 0; ft < 2; ft++) {
            const int nrow = (2 * wp + ft) * 16 + (jm >> 1) * 8 + nr;
            const int kb   = (jm & 1) * 16;
            #pragma unroll
            for (int kc = 0; kc < 4; kc++)
                ldsm_x4(Bf[ft][kc][0], Bf[ft][kc][1], Bf[ft][kc][2], Bf[ft][kc][3],
                        sb + SM_W + sw128((uint32_t)nrow * 128 + kc * 32 + kb));
        }
    }

    const int KS = 32768;                      // k-stride in scatter tensors
    const int r  = lane >> 2;                  // D-frag row within m8
    const int q  = lane & 3;                   // D-frag col pair
    const int e  = q & 1;                      // 0: j={0,1} holder, 1: j={2,3}
    const int ii = q >> 1;                     // kernel row within n8 tile
    const int hh = r + 8 * e;

    for (int t = cidx; t < TILES_PER_G; t += CTAS_PER_G) {
        const int bb = t >> 5;                 // batch
        const int w0 = (t & 31) * 2;           // first of two w-rows in this tile

        __syncthreads();                       // all A reads of previous X done

        // ---- Build X tile: 128 pos x 64 ch fp16, SW128, program-ordered scatter.
        if (tid < 128) {
            const int pp = tid;
            const int h  = pp & 63;
            const int w  = w0 + (pp >> 6);
            char* xrow = smc + SM_X + pp * 128;
            const uint4 z = make_uint4(0, 0, 0, 0);
            #pragma unroll
            for (int z4 = 0; z4 < 8; z4++)
                *reinterpret_cast<uint4*>(xrow + z4 * 16) = z;
            const int base = (((bb * 4) * 8 + g) << 12) + w * 64 + h;
            const uint32_t rsw = ((uint32_t)pp & 7) << 4;
            #pragma unroll
            for (int k = 0; k < 4; k++) {      // pos scatter (k ascending)
                const int    c = __ldg(indp + base + k * KS);
                const __half v = __float2half(__ldg(valp + base + k * KS));
                *reinterpret_cast<__half*>(xrow + (((uint32_t)(2 * c)) ^ rsw)) = v;
            }
            #pragma unroll
            for (int k = 0; k < 4; k++) {      // neg scatter overwrites pos
                const int    c = __ldg(indn + base + k * KS);
                const __half v = __float2half(__ldg(valn + base + k * KS));
                *reinterpret_cast<__half*>(xrow + (((uint32_t)(2 * c)) ^ rsw)) = v;
            }
        }
        __syncthreads();

        #pragma unroll 1
        for (int s = 0; s < 8; s++) {
            // D for both features (16 floats live).
            float d00 = 0.f, d01 = 0.f, d02 = 0.f, d03 = 0.f;   // ft0 taps 0..7
            float d04 = 0.f, d05 = 0.f, d06 = 0.f, d07 = 0.f;   // ft0 taps 8..15
            float d10 = 0.f, d11 = 0.f, d12 = 0.f, d13 = 0.f;   // ft1 taps 0..7
            float d14 = 0.f, d15 = 0.f, d16 = 0.f, d17 = 0.f;   // ft1 taps 8..15

            // Stream A one k-chunk at a time (4 transient regs), feed 4 MMAs each.
            // Exact per-kc swizzle: row*128 + ((colb | kc*32) ^ mask), mask=(row&7)<<4.
            const uint32_t arow  = (uint32_t)(16 * s + (lane & 15));
            const uint32_t colb  = (uint32_t)((lane >> 4) * 16);
            const uint32_t mask  = (arow & 7u) << 4;
            const uint32_t arowb = sb + SM_X + arow * 128;
            #pragma unroll
            for (int kc = 0; kc < 4; kc++) {
                uint32_t a0, a1, a2, a3;
                ldsm_x4(a0, a1, a2, a3, arowb + ((colb | (uint32_t)(kc * 32)) ^ mask));
                mma16816(d00, d01, d02, d03, a0, a1, a2, a3, Bf[0][kc][0], Bf[0][kc][1]);
                mma16816(d04, d05, d06, d07, a0, a1, a2, a3, Bf[0][kc][2], Bf[0][kc][3]);
                mma16816(d10, d11, d12, d13, a0, a1, a2, a3, Bf[1][kc][0], Bf[1][kc][1]);
                mma16816(d14, d15, d16, d17, a0, a1, a2, a3, Bf[1][kc][2], Bf[1][kc][3]);
            }

            const int wo = w0 + (s >> 2);
            const int h0 = 16 * (s & 3);
            float* ob0 = out + (((size_t)(bb * 256 + g * 32 + 2 * wp)) * 256
                                + 4 * wo) * 256 + 4 * h0;

            // ---- Shuffle epilogue (pair q <-> q^1 assembles along-j float4s).
            #pragma unroll
            for (int ft = 0; ft < 2; ft++) {
                float t0x = ft ? d10 : d00, t0y = ft ? d11 : d01;
                float t2x = ft ? d12 : d02, t2y = ft ? d13 : d03;
                float t4x = ft ? d14 : d04, t4y = ft ? d15 : d05;
                float t6x = ft ? d16 : d06, t6y = ft ? d17 : d07;
                float* obase = ob0 + (size_t)ft * 65536;     // next feature: +256*256

                {   // n8 tile 0: kernel row i = ii
                    float sx = e ? t0x : t2x;
                    float sy = e ? t0y : t2y;
                    float rx = __shfl_xor_sync(0xFFFFFFFFu, sx, 1);
                    float ry = __shfl_xor_sync(0xFFFFFFFFu, sy, 1);
                    float4 v = e ? make_float4(rx, ry, t2x, t2y)
                                 : make_float4(t0x, t0y, rx, ry);
                    *reinterpret_cast<float4*>(obase + (size_t)ii * 256 + 4 * hh) = v;
                }
                {   // n8 tile 1: kernel row i = 2 + ii
                    float sx = e ? t4x : t6x;
                    float sy = e ? t4y : t6y;
                    float rx = __shfl_xor_sync(0xFFFFFFFFu, sx, 1);
                    float ry = __shfl_xor_sync(0xFFFFFFFFu, sy, 1);
                    float4 v = e ? make_float4(rx, ry, t6x, t6y)
                                 : make_float4(t4x, t4y, rx, ry);
                    *reinterpret_cast<float4*>(obase + (size_t)(2 + ii) * 256 + 4 * hh) = v;
                }
            }
        }
    }
}
}  // namespace

extern "C" void kernel_launch(void* const* d_in, const int* in_sizes, int n_in,
                              void* d_out, int out_size) {
    const int*   indp = (const int*)d_in[0];
    const int*   indn = (const int*)d_in[1];
    const float* valp = (const float*)d_in[2];
    const float* valn = (const float*)d_in[3];
    const float* wgt  = (const float*)d_in[4];
    float* out = (float*)d_out;

    cudaFuncSetAttribute(deconv_hmma_kernel,
                         cudaFuncAttributeMaxDynamicSharedMemorySize, SMEM_TOTAL);
    cudaFuncSetAttribute(deconv_hmma_kernel,
                         cudaFuncAttributePreferredSharedMemoryCarveout, 100);
    deconv_hmma_kernel<<<8 * CTAS_PER_G, THREADS, SMEM_TOTAL>>>(
        indp, indn, valp, valn, wgt, out);
}

// round 14
// speedup vs baseline: 1.2162x; 1.0038x over previous
#include <cuda_runtime.h>
#include <cuda_fp16.h>
#include <cstdint>

namespace {
constexpr int THREADS = 512;
constexpr int CTAS_PER_G = 37;                // 8*37 = 296 = 2 CTAs x 148 SMs
constexpr int TILES_PER_G = 256;              // 64-position tiles (one w-row each)

// SMEM byte layout
constexpr int SM_X = 0;                       // X: 64 pos x 64 f16 (128B rows, SW128) = 8KB
constexpr int SM_W = 8192;                    // W^T: 512 n x 64 f16 (128B rows, SW128) = 64KB
constexpr int SMEM_TOTAL = 73728;             // -> 2 CTAs/SM

__device__ __forceinline__ uint32_t smem_u32(const void* p) {
    uint32_t a;
    asm("{ .reg .u64 t; cvta.to.shared.u64 t, %1; cvt.u32.u64 %0, t; }" : "=r"(a) : "l"(p));
    return a;
}
__device__ __forceinline__ uint32_t sw128(uint32_t b) { return b ^ ((b >> 3) & 0x70); }

__device__ __forceinline__ void ldsm_x4(uint32_t& r0, uint32_t& r1, uint32_t& r2,
                                        uint32_t& r3, uint32_t addr) {
    asm volatile("ldmatrix.sync.aligned.m8n8.x4.shared.b16 {%0,%1,%2,%3}, [%4];"
                 : "=r"(r0), "=r"(r1), "=r"(r2), "=r"(r3) : "r"(addr));
}
__device__ __forceinline__ void mma16816(float& d0, float& d1, float& d2, float& d3,
                                         uint32_t a0, uint32_t a1, uint32_t a2, uint32_t a3,
                                         uint32_t b0, uint32_t b1) {
    asm volatile(
        "mma.sync.aligned.m16n8k16.row.col.f32.f16.f16.f32 "
        "{%0,%1,%2,%3}, {%4,%5,%6,%7}, {%8,%9}, {%0,%1,%2,%3};"
        : "+f"(d0), "+f"(d1), "+f"(d2), "+f"(d3)
        : "r"(a0), "r"(a1), "r"(a2), "r"(a3), "r"(b0), "r"(b1));
}

__global__ void __launch_bounds__(THREADS, 2)
deconv_hmma_kernel(const int* __restrict__ indp, const int* __restrict__ indn,
                   const float* __restrict__ valp, const float* __restrict__ valn,
                   const float* __restrict__ wgt, float* __restrict__ out)
{
    extern __shared__ char smc[];
    const uint32_t sb = smem_u32(smc);

    const int tid  = threadIdx.x;
    const int lane = tid & 31;
    const int wp   = tid >> 5;

    const int g    = blockIdx.x / CTAS_PER_G;
    const int cidx = blockIdx.x % CTAS_PER_G;

    // ---- Build W^T in smem: Wsm[n][c] = (f16) wgt[g*32768 + c*512 + n], SW128 rows.
    {
        const int n = tid;                     // 0..511
        #pragma unroll
        for (int c8 = 0; c8 < 8; c8++) {
            const int c0 = c8 * 8;
            unsigned pk[4];
            #pragma unroll
            for (int q4 = 0; q4 < 4; q4++) {
                float f0 = __ldg(wgt + (size_t)g * 32768 + (size_t)(c0 + 2*q4    ) * 512 + n);
                float f1 = __ldg(wgt + (size_t)g * 32768 + (size_t)(c0 + 2*q4 + 1) * 512 + n);
                __half2 h = __floats2half2_rn(f0, f1);
                pk[q4] = *reinterpret_cast<unsigned*>(&h);
            }
            *reinterpret_cast<uint4*>(smc + SM_W + sw128((uint32_t)n * 128 + c0 * 2)) =
                make_uint4(pk[0], pk[1], pk[2], pk[3]);
        }
    }
    __syncthreads();

    // ---- B fragments for this warp's two features: loaded ONCE, kernel-lifetime.
    uint32_t Bf[2][4][4];                      // [feat][k-chunk][frag]  (32 regs)
    {
        const int nr = lane & 7;
        const int jm = lane >> 3;
        #pragma unroll
        for (int ft = 0; ft < 2; ft++) {
            const int nrow = (2 * wp + ft) * 16 + (jm >> 1) * 8 + nr;
            const int kb   = (jm & 1) * 16;
            #pragma unroll
            for (int kc = 0; kc < 4; kc++)
                ldsm_x4(Bf[ft][kc][0], Bf[ft][kc][1], Bf[ft][kc][2], Bf[ft][kc][3],
                        sb + SM_W + sw128((uint32_t)nrow * 128 + kc * 32 + kb));
        }
    }

    const int KS = 32768;                      // k-stride in scatter tensors
    const int r  = lane >> 2;                  // D-frag row within m8
    const int q  = lane & 3;                   // D-frag col pair
    const int e  = q & 1;                      // 0: j={0,1} holder, 1: j={2,3}
    const int ii = q >> 1;                     // kernel row within n8 tile
    const int hh = r + 8 * e;

    for (int t = cidx; t < TILES_PER_G; t += CTAS_PER_G) {
        const int bb = t >> 6;                 // batch
        const int w  = t & 63;                 // this tile's w-row

        __syncthreads();                       // all A reads of previous X done

        // ---- Build X tile: 64 pos x 64 ch fp16, SW128. Thread h owns row h
        //      (zero then ordered scatter, same thread => no sync needed between).
        if (tid < 64) {
            const int h = tid;
            char* xrow = smc + SM_X + h * 128;
            const uint4 z = make_uint4(0, 0, 0, 0);
            #pragma unroll
            for (int z4 = 0; z4 < 8; z4++)
                *reinterpret_cast<uint4*>(xrow + z4 * 16) = z;
            const int base = (((bb * 32) + g) << 12) + w * 64 + h;
            const uint32_t rsw = ((uint32_t)h & 7) << 4;
            #pragma unroll
            for (int k = 0; k < 4; k++) {      // pos scatter (k ascending)
                const int    c = __ldg(indp + base + k * KS);
                const __half v = __float2half(__ldg(valp + base + k * KS));
                *reinterpret_cast<__half*>(xrow + (((uint32_t)(2 * c)) ^ rsw)) = v;
            }
            #pragma unroll
            for (int k = 0; k < 4; k++) {      // neg scatter overwrites pos
                const int    c = __ldg(indn + base + k * KS);
                const __half v = __float2half(__ldg(valn + base + k * KS));
                *reinterpret_cast<__half*>(xrow + (((uint32_t)(2 * c)) ^ rsw)) = v;
            }
        }
        __syncthreads();

        #pragma unroll 1
        for (int s = 0; s < 4; s++) {
            // D for both features (16 floats live).
            float d00 = 0.f, d01 = 0.f, d02 = 0.f, d03 = 0.f;   // ft0 taps 0..7
            float d04 = 0.f, d05 = 0.f, d06 = 0.f, d07 = 0.f;   // ft0 taps 8..15
            float d10 = 0.f, d11 = 0.f, d12 = 0.f, d13 = 0.f;   // ft1 taps 0..7
            float d14 = 0.f, d15 = 0.f, d16 = 0.f, d17 = 0.f;   // ft1 taps 8..15

            // Stream A one k-chunk at a time. Exact per-kc swizzle:
            // row*128 + ((colb | kc*32) ^ mask), mask = (row&7)<<4.
            const uint32_t arow  = (uint32_t)(16 * s + (lane & 15));
            const uint32_t colb  = (uint32_t)((lane >> 4) * 16);
            const uint32_t mask  = (arow & 7u) << 4;
            const uint32_t arowb = sb + SM_X + arow * 128;
            #pragma unroll
            for (int kc = 0; kc < 4; kc++) {
                uint32_t a0, a1, a2, a3;
                ldsm_x4(a0, a1, a2, a3, arowb + ((colb | (uint32_t)(kc * 32)) ^ mask));
                mma16816(d00, d01, d02, d03, a0, a1, a2, a3, Bf[0][kc][0], Bf[0][kc][1]);
                mma16816(d04, d05, d06, d07, a0, a1, a2, a3, Bf[0][kc][2], Bf[0][kc][3]);
                mma16816(d10, d11, d12, d13, a0, a1, a2, a3, Bf[1][kc][0], Bf[1][kc][1]);
                mma16816(d14, d15, d16, d17, a0, a1, a2, a3, Bf[1][kc][2], Bf[1][kc][3]);
            }

            const int h0 = 16 * s;
            float* ob0 = out + (((size_t)(bb * 256 + g * 32 + 2 * wp)) * 256
                                + 4 * w) * 256 + 4 * h0;

            // ---- Shuffle epilogue (pair q <-> q^1 assembles along-j float4s).
            #pragma unroll
            for (int ft = 0; ft < 2; ft++) {
                float t0x = ft ? d10 : d00, t0y = ft ? d11 : d01;
                float t2x = ft ? d12 : d02, t2y = ft ? d13 : d03;
                float t4x = ft ? d14 : d04, t4y = ft ? d15 : d05;
                float t6x = ft ? d16 : d06, t6y = ft ? d17 : d07;
                float* obase = ob0 + (size_t)ft * 65536;     // next feature: +256*256

                {   // n8 tile 0: kernel row i = ii
                    float sx = e ? t0x : t2x;
                    float sy = e ? t0y : t2y;
                    float rx = __shfl_xor_sync(0xFFFFFFFFu, sx, 1);
                    float ry = __shfl_xor_sync(0xFFFFFFFFu, sy, 1);
                    float4 v = e ? make_float4(rx, ry, t2x, t2y)
                                 : make_float4(t0x, t0y, rx, ry);
                    *reinterpret_cast<float4*>(obase + (size_t)ii * 256 + 4 * hh) = v;
                }
                {   // n8 tile 1: kernel row i = 2 + ii
                    float sx = e ? t4x : t6x;
                    float sy = e ? t4y : t6y;
                    float rx = __shfl_xor_sync(0xFFFFFFFFu, sx, 1);
                    float ry = __shfl_xor_sync(0xFFFFFFFFu, sy, 1);
                    float4 v = e ? make_float4(rx, ry, t6x, t6y)
                                 : make_float4(t4x, t4y, rx, ry);
                    *reinterpret_cast<float4*>(obase + (size_t)(2 + ii) * 256 + 4 * hh) = v;
                }
            }
        }
    }
}
}  // namespace

extern "C" void kernel_launch(void* const* d_in, const int* in_sizes, int n_in,
                              void* d_out, int out_size) {
    const int*   indp = (const int*)d_in[0];
    const int*   indn = (const int*)d_in[1];
    const float* valp = (const float*)d_in[2];
    const float* valn = (const float*)d_in[3];
    const float* wgt  = (const float*)d_in[4];
    float* out = (float*)d_out;

    cudaFuncSetAttribute(deconv_hmma_kernel,
                         cudaFuncAttributeMaxDynamicSharedMemorySize, SMEM_TOTAL);
    cudaFuncSetAttribute(deconv_hmma_kernel,
                         cudaFuncAttributePreferredSharedMemoryCarveout, 100);
    deconv_hmma_kernel<<<8 * CTAS_PER_G, THREADS, SMEM_TOTAL>>>(
        indp, indn, valp, valn, wgt, out);
}

// round 15
// speedup vs baseline: 1.4095x; 1.1590x over previous
#include <cuda_runtime.h>
#include <cuda_fp16.h>
#include <cstdint>

namespace {
constexpr int THREADS = 512;
constexpr int CTAS_PER_G = 37;                // 8*37 = 296 = 2 CTAs x 148 SMs
constexpr int TILES_PER_G = 256;              // 64-position tiles (one w-row each)

// SMEM byte layout: two X buffers (double-buffered) + W
constexpr int SM_X0 = 0;                      // X buf0: 64 pos x 64 f16 (SW128) = 8KB
constexpr int SM_X1 = 8192;                   // X buf1: 8KB
constexpr int SM_W  = 16384;                  // W^T: 512 n x 64 f16 (SW128) = 64KB
constexpr int SMEM_TOTAL = 81920;             // -> 2 CTAs/SM (160KB/SM)

__device__ __forceinline__ uint32_t smem_u32(const void* p) {
    uint32_t a;
    asm("{ .reg .u64 t; cvta.to.shared.u64 t, %1; cvt.u32.u64 %0, t; }" : "=r"(a) : "l"(p));
    return a;
}
__device__ __forceinline__ uint32_t sw128(uint32_t b) { return b ^ ((b >> 3) & 0x70); }

__device__ __forceinline__ void ldsm_x4(uint32_t& r0, uint32_t& r1, uint32_t& r2,
                                        uint32_t& r3, uint32_t addr) {
    asm volatile("ldmatrix.sync.aligned.m8n8.x4.shared.b16 {%0,%1,%2,%3}, [%4];"
                 : "=r"(r0), "=r"(r1), "=r"(r2), "=r"(r3) : "r"(addr));
}
__device__ __forceinline__ void mma16816(float& d0, float& d1, float& d2, float& d3,
                                         uint32_t a0, uint32_t a1, uint32_t a2, uint32_t a3,
                                         uint32_t b0, uint32_t b1) {
    asm volatile(
        "mma.sync.aligned.m16n8k16.row.col.f32.f16.f16.f32 "
        "{%0,%1,%2,%3}, {%4,%5,%6,%7}, {%8,%9}, {%0,%1,%2,%3};"
        : "+f"(d0), "+f"(d1), "+f"(d2), "+f"(d3)
        : "r"(a0), "r"(a1), "r"(a2), "r"(a3), "r"(b0), "r"(b1));
}

__global__ void __launch_bounds__(THREADS, 2)
deconv_hmma_kernel(const int* __restrict__ indp, const int* __restrict__ indn,
                   const float* __restrict__ valp, const float* __restrict__ valn,
                   const float* __restrict__ wgt, float* __restrict__ out)
{
    extern __shared__ char smc[];
    const uint32_t sb = smem_u32(smc);

    const int tid  = threadIdx.x;
    const int lane = tid & 31;
    const int wp   = tid >> 5;

    const int g    = blockIdx.x / CTAS_PER_G;
    const int cidx = blockIdx.x % CTAS_PER_G;
    const int KS   = 32768;                    // k-stride in scatter tensors

    // ---- X-tile builder: thread h (0..63) owns row h of the chosen buffer.
    //      Zero then program-ordered scatter (same thread => last-write-wins free).
    auto build_x = [&](int t, int buf) {
        if (tid < 64) {
            const int bb = t >> 6;
            const int w  = t & 63;
            const int h  = tid;
            char* xrow = smc + (buf ? SM_X1 : SM_X0) + h * 128;
            const uint4 z = make_uint4(0, 0, 0, 0);
            #pragma unroll
            for (int z4 = 0; z4 < 8; z4++)
                *reinterpret_cast<uint4*>(xrow + z4 * 16) = z;
            const int base = (((bb * 32) + g) << 12) + w * 64 + h;
            const uint32_t rsw = ((uint32_t)h & 7) << 4;
            #pragma unroll
            for (int k = 0; k < 4; k++) {      // pos scatter (k ascending)
                const int    c = __ldg(indp + base + k * KS);
                const __half v = __float2half(__ldg(valp + base + k * KS));
                *reinterpret_cast<__half*>(xrow + (((uint32_t)(2 * c)) ^ rsw)) = v;
            }
            #pragma unroll
            for (int k = 0; k < 4; k++) {      // neg scatter overwrites pos
                const int    c = __ldg(indn + base + k * KS);
                const __half v = __float2half(__ldg(valn + base + k * KS));
                *reinterpret_cast<__half*>(xrow + (((uint32_t)(2 * c)) ^ rsw)) = v;
            }
        }
    };

    // ---- Build W^T in smem: Wsm[n][c] = (f16) wgt[g*32768 + c*512 + n], SW128 rows.
    {
        const int n = tid;                     // 0..511
        #pragma unroll
        for (int c8 = 0; c8 < 8; c8++) {
            const int c0 = c8 * 8;
            unsigned pk[4];
            #pragma unroll
            for (int q4 = 0; q4 < 4; q4++) {
                float f0 = __ldg(wgt + (size_t)g * 32768 + (size_t)(c0 + 2*q4    ) * 512 + n);
                float f1 = __ldg(wgt + (size_t)g * 32768 + (size_t)(c0 + 2*q4 + 1) * 512 + n);
                __half2 h = __floats2half2_rn(f0, f1);
                pk[q4] = *reinterpret_cast<unsigned*>(&h);
            }
            *reinterpret_cast<uint4*>(smc + SM_W + sw128((uint32_t)n * 128 + c0 * 2)) =
                make_uint4(pk[0], pk[1], pk[2], pk[3]);
        }
    }
    build_x(cidx, 0);                          // prologue: first tile into buf0
    __syncthreads();

    // ---- B fragments for this warp's two features: loaded ONCE, kernel-lifetime.
    uint32_t Bf[2][4][4];                      // [feat][k-chunk][frag]  (32 regs)
    {
        const int nr = lane & 7;
        const int jm = lane >> 3;
        #pragma unroll
        for (int ft = 0; ft < 2; ft++) {
            const int nrow = (2 * wp + ft) * 16 + (jm >> 1) * 8 + nr;
            const int kb   = (jm & 1) * 16;
            #pragma unroll
            for (int kc = 0; kc < 4; kc++)
                ldsm_x4(Bf[ft][kc][0], Bf[ft][kc][1], Bf[ft][kc][2], Bf[ft][kc][3],
                        sb + SM_W + sw128((uint32_t)nrow * 128 + kc * 32 + kb));
        }
    }

    const int r  = lane >> 2;                  // D-frag row within m8
    const int q  = lane & 3;                   // D-frag col pair
    const int e  = q & 1;                      // 0: j={0,1} holder, 1: j={2,3}
    const int ii = q >> 1;                     // kernel row within n8 tile
    const int hh = r + 8 * e;

    int buf = 0;
    for (int t = cidx; t < TILES_PER_G; t += CTAS_PER_G) {
        // ---- Producer: issue next tile's build into the other buffer (overlaps MMA).
        const int tn = t + CTAS_PER_G;
        if (tn < TILES_PER_G) build_x(tn, buf ^ 1);

        const int bb = t >> 6;                 // batch
        const int w  = t & 63;                 // this tile's w-row
        const uint32_t xb = sb + (buf ? SM_X1 : SM_X0);

        #pragma unroll 1
        for (int s = 0; s < 4; s++) {
            // D for both features (16 floats live).
            float d00 = 0.f, d01 = 0.f, d02 = 0.f, d03 = 0.f;   // ft0 taps 0..7
            float d04 = 0.f, d05 = 0.f, d06 = 0.f, d07 = 0.f;   // ft0 taps 8..15
            float d10 = 0.f, d11 = 0.f, d12 = 0.f, d13 = 0.f;   // ft1 taps 0..7
            float d14 = 0.f, d15 = 0.f, d16 = 0.f, d17 = 0.f;   // ft1 taps 8..15

            // Stream A one k-chunk at a time. Exact per-kc swizzle:
            // row*128 + ((colb | kc*32) ^ mask), mask = (row&7)<<4.
            const uint32_t arow  = (uint32_t)(16 * s + (lane & 15));
            const uint32_t colb  = (uint32_t)((lane >> 4) * 16);
            const uint32_t mask  = (arow & 7u) << 4;
            const uint32_t arowb = xb + arow * 128;
            #pragma unroll
            for (int kc = 0; kc < 4; kc++) {
                uint32_t a0, a1, a2, a3;
                ldsm_x4(a0, a1, a2, a3, arowb + ((colb | (uint32_t)(kc * 32)) ^ mask));
                mma16816(d00, d01, d02, d03, a0, a1, a2, a3, Bf[0][kc][0], Bf[0][kc][1]);
                mma16816(d04, d05, d06, d07, a0, a1, a2, a3, Bf[0][kc][2], Bf[0][kc][3]);
                mma16816(d10, d11, d12, d13, a0, a1, a2, a3, Bf[1][kc][0], Bf[1][kc][1]);
                mma16816(d14, d15, d16, d17, a0, a1, a2, a3, Bf[1][kc][2], Bf[1][kc][3]);
            }

            const int h0 = 16 * s;
            float* ob0 = out + (((size_t)(bb * 256 + g * 32 + 2 * wp)) * 256
                                + 4 * w) * 256 + 4 * h0;

            // ---- Shuffle epilogue (pair q <-> q^1 assembles along-j float4s).
            #pragma unroll
            for (int ft = 0; ft < 2; ft++) {
                float t0x = ft ? d10 : d00, t0y = ft ? d11 : d01;
                float t2x = ft ? d12 : d02, t2y = ft ? d13 : d03;
                float t4x = ft ? d14 : d04, t4y = ft ? d15 : d05;
                float t6x = ft ? d16 : d06, t6y = ft ? d17 : d07;
                float* obase = ob0 + (size_t)ft * 65536;     // next feature: +256*256

                {   // n8 tile 0: kernel row i = ii
                    float sx = e ? t0x : t2x;
                    float sy = e ? t0y : t2y;
                    float rx = __shfl_xor_sync(0xFFFFFFFFu, sx, 1);
                    float ry = __shfl_xor_sync(0xFFFFFFFFu, sy, 1);
                    float4 v = e ? make_float4(rx, ry, t2x, t2y)
                                 : make_float4(t0x, t0y, rx, ry);
                    *reinterpret_cast<float4*>(obase + (size_t)ii * 256 + 4 * hh) = v;
                }
                {   // n8 tile 1: kernel row i = 2 + ii
                    float sx = e ? t4x : t6x;
                    float sy = e ? t4y : t6y;
                    float rx = __shfl_xor_sync(0xFFFFFFFFu, sx, 1);
                    float ry = __shfl_xor_sync(0xFFFFFFFFu, sy, 1);
                    float4 v = e ? make_float4(rx, ry, t6x, t6y)
                                 : make_float4(t4x, t4y, rx, ry);
                    *reinterpret_cast<float4*>(obase + (size_t)(2 + ii) * 256 + 4 * hh) = v;
                }
            }
        }

        // One joint barrier: next-tile build STS complete AND current reads done.
        __syncthreads();
        buf ^= 1;
    }
}
}  // namespace

extern "C" void kernel_launch(void* const* d_in, const int* in_sizes, int n_in,
                              void* d_out, int out_size) {
    const int*   indp = (const int*)d_in[0];
    const int*   indn = (const int*)d_in[1];
    const float* valp = (const float*)d_in[2];
    const float* valn = (const float*)d_in[3];
    const float* wgt  = (const float*)d_in[4];
    float* out = (float*)d_out;

    cudaFuncSetAttribute(deconv_hmma_kernel,
                         cudaFuncAttributeMaxDynamicSharedMemorySize, SMEM_TOTAL);
    cudaFuncSetAttribute(deconv_hmma_kernel,
                         cudaFuncAttributePreferredSharedMemoryCarveout, 100);
    deconv_hmma_kernel<<<8 * CTAS_PER_G, THREADS, SMEM_TOTAL>>>(
        indp, indn, valp, valn, wgt, out);
}

// round 16
// speedup vs baseline: 1.4974x; 1.0623x over previous
#include <cuda_runtime.h>
#include <cuda_fp16.h>
#include <cstdint>

namespace {
constexpr int THREADS = 256;                  // 8 warps; 2 CTAs/SM => 128-reg budget
constexpr int CTAS_PER_G = 37;                // 8*37 = 296 = 2 CTAs x 148 SMs
constexpr int TILES_PER_G = 256;              // 64-position tiles (one w-row each)

// SMEM byte layout: two X buffers (double-buffered) + W
constexpr int SM_X0 = 0;                      // X buf0: 64 pos x 64 f16 (SW128) = 8KB
constexpr int SM_X1 = 8192;                   // X buf1: 8KB
constexpr int SM_W  = 16384;                  // W^T: 512 n x 64 f16 (SW128) = 64KB
constexpr int SMEM_TOTAL = 81920;             // -> 2 CTAs/SM (160KB/SM)

__device__ __forceinline__ uint32_t smem_u32(const void* p) {
    uint32_t a;
    asm("{ .reg .u64 t; cvta.to.shared.u64 t, %1; cvt.u32.u64 %0, t; }" : "=r"(a) : "l"(p));
    return a;
}
__device__ __forceinline__ uint32_t sw128(uint32_t b) { return b ^ ((b >> 3) & 0x70); }

__device__ __forceinline__ void ldsm_x4(uint32_t& r0, uint32_t& r1, uint32_t& r2,
                                        uint32_t& r3, uint32_t addr) {
    asm volatile("ldmatrix.sync.aligned.m8n8.x4.shared.b16 {%0,%1,%2,%3}, [%4];"
                 : "=r"(r0), "=r"(r1), "=r"(r2), "=r"(r3) : "r"(addr));
}
__device__ __forceinline__ void mma16816(float& d0, float& d1, float& d2, float& d3,
                                         uint32_t a0, uint32_t a1, uint32_t a2, uint32_t a3,
                                         uint32_t b0, uint32_t b1) {
    asm volatile(
        "mma.sync.aligned.m16n8k16.row.col.f32.f16.f16.f32 "
        "{%0,%1,%2,%3}, {%4,%5,%6,%7}, {%8,%9}, {%0,%1,%2,%3};"
        : "+f"(d0), "+f"(d1), "+f"(d2), "+f"(d3)
        : "r"(a0), "r"(a1), "r"(a2), "r"(a3), "r"(b0), "r"(b1));
}

__global__ void __launch_bounds__(THREADS, 2)
deconv_hmma_kernel(const int* __restrict__ indp, const int* __restrict__ indn,
                   const float* __restrict__ valp, const float* __restrict__ valn,
                   const float* __restrict__ wgt, float* __restrict__ out)
{
    extern __shared__ char smc[];
    const uint32_t sb = smem_u32(smc);

    const int tid  = threadIdx.x;
    const int lane = tid & 31;
    const int wp   = tid >> 5;                 // 0..7

    const int g    = blockIdx.x / CTAS_PER_G;
    const int cidx = blockIdx.x % CTAS_PER_G;
    const int KS   = 32768;                    // k-stride in scatter tensors

    // ---- X-tile builder: thread h (0..63) owns row h of the chosen buffer.
    auto build_x = [&](int t, int buf) {
        if (tid < 64) {
            const int bb = t >> 6;
            const int w  = t & 63;
            const int h  = tid;
            char* xrow = smc + (buf ? SM_X1 : SM_X0) + h * 128;
            const uint4 z = make_uint4(0, 0, 0, 0);
            #pragma unroll
            for (int z4 = 0; z4 < 8; z4++)
                *reinterpret_cast<uint4*>(xrow + z4 * 16) = z;
            const int base = (((bb * 32) + g) << 12) + w * 64 + h;
            const uint32_t rsw = ((uint32_t)h & 7) << 4;
            #pragma unroll
            for (int k = 0; k < 4; k++) {      // pos scatter (k ascending)
                const int    c = __ldg(indp + base + k * KS);
                const __half v = __float2half(__ldg(valp + base + k * KS));
                *reinterpret_cast<__half*>(xrow + (((uint32_t)(2 * c)) ^ rsw)) = v;
            }
            #pragma unroll
            for (int k = 0; k < 4; k++) {      // neg scatter overwrites pos
                const int    c = __ldg(indn + base + k * KS);
                const __half v = __float2half(__ldg(valn + base + k * KS));
                *reinterpret_cast<__half*>(xrow + (((uint32_t)(2 * c)) ^ rsw)) = v;
            }
        }
    };

    // ---- Build W^T in smem: Wsm[n][c] = (f16) wgt[g*32768 + c*512 + n], SW128 rows.
    for (int n = tid; n < 512; n += THREADS) {
        #pragma unroll
        for (int c8 = 0; c8 < 8; c8++) {
            const int c0 = c8 * 8;
            unsigned pk[4];
            #pragma unroll
            for (int q4 = 0; q4 < 4; q4++) {
                float f0 = __ldg(wgt + (size_t)g * 32768 + (size_t)(c0 + 2*q4    ) * 512 + n);
                float f1 = __ldg(wgt + (size_t)g * 32768 + (size_t)(c0 + 2*q4 + 1) * 512 + n);
                __half2 h = __floats2half2_rn(f0, f1);
                pk[q4] = *reinterpret_cast<unsigned*>(&h);
            }
            *reinterpret_cast<uint4*>(smc + SM_W + sw128((uint32_t)n * 128 + c0 * 2)) =
                make_uint4(pk[0], pk[1], pk[2], pk[3]);
        }
    }
    build_x(cidx, 0);                          // prologue: first tile into buf0
    __syncthreads();

    // ---- B fragments for this warp's FOUR features: loaded ONCE (64 regs).
    uint32_t Bf[4][4][4];                      // [feat][k-chunk][frag]
    {
        const int nr = lane & 7;
        const int jm = lane >> 3;
        #pragma unroll
        for (int ft = 0; ft < 4; ft++) {
            const int nrow = (4 * wp + ft) * 16 + (jm >> 1) * 8 + nr;
            const int kb   = (jm & 1) * 16;
            #pragma unroll
            for (int kc = 0; kc < 4; kc++)
                ldsm_x4(Bf[ft][kc][0], Bf[ft][kc][1], Bf[ft][kc][2], Bf[ft][kc][3],
                        sb + SM_W + sw128((uint32_t)nrow * 128 + kc * 32 + kb));
        }
    }

    const int r  = lane >> 2;                  // D-frag row within m8
    const int q  = lane & 3;                   // D-frag col pair
    const int e  = q & 1;                      // 0: j={0,1} holder, 1: j={2,3}
    const int ii = q >> 1;                     // kernel row within n8 tile
    const int hh = r + 8 * e;

    int buf = 0;
    for (int t = cidx; t < TILES_PER_G; t += CTAS_PER_G) {
        // ---- Producer: issue next tile's build into the other buffer (overlaps MMA).
        const int tn = t + CTAS_PER_G;
        if (tn < TILES_PER_G) build_x(tn, buf ^ 1);

        const int bb = t >> 6;                 // batch
        const int w  = t & 63;                 // this tile's w-row
        const uint32_t xb = sb + (buf ? SM_X1 : SM_X0);

        #pragma unroll 1
        for (int s = 0; s < 4; s++) {
            float d[4][8];                     // [feat][tile0 0..3 | tile1 4..7]
            #pragma unroll
            for (int ft = 0; ft < 4; ft++)
                #pragma unroll
                for (int z = 0; z < 8; z++) d[ft][z] = 0.f;

            // Stream A one k-chunk at a time; exact per-kc swizzle.
            const uint32_t arow  = (uint32_t)(16 * s + (lane & 15));
            const uint32_t colb  = (uint32_t)((lane >> 4) * 16);
            const uint32_t mask  = (arow & 7u) << 4;
            const uint32_t arowb = xb + arow * 128;
            #pragma unroll
            for (int kc = 0; kc < 4; kc++) {
                uint32_t a0, a1, a2, a3;
                ldsm_x4(a0, a1, a2, a3, arowb + ((colb | (uint32_t)(kc * 32)) ^ mask));
                #pragma unroll
                for (int ft = 0; ft < 4; ft++) {
                    mma16816(d[ft][0], d[ft][1], d[ft][2], d[ft][3],
                             a0, a1, a2, a3, Bf[ft][kc][0], Bf[ft][kc][1]);
                    mma16816(d[ft][4], d[ft][5], d[ft][6], d[ft][7],
                             a0, a1, a2, a3, Bf[ft][kc][2], Bf[ft][kc][3]);
                }
            }

            const int h0 = 16 * s;
            float* ob0 = out + (((size_t)(bb * 256 + g * 32 + 4 * wp)) * 256
                                + 4 * w) * 256 + 4 * h0;

            // ---- Shuffle epilogue (pair q <-> q^1 assembles along-j float4s).
            #pragma unroll
            for (int ft = 0; ft < 4; ft++) {
                float* obase = ob0 + (size_t)ft * 65536;     // next feature: +256*256
                {   // n8 tile 0: kernel row i = ii
                    float sx = e ? d[ft][0] : d[ft][2];
                    float sy = e ? d[ft][1] : d[ft][3];
                    float rx = __shfl_xor_sync(0xFFFFFFFFu, sx, 1);
                    float ry = __shfl_xor_sync(0xFFFFFFFFu, sy, 1);
                    float4 v = e ? make_float4(rx, ry, d[ft][2], d[ft][3])
                                 : make_float4(d[ft][0], d[ft][1], rx, ry);
                    *reinterpret_cast<float4*>(obase + (size_t)ii * 256 + 4 * hh) = v;
                }
                {   // n8 tile 1: kernel row i = 2 + ii
                    float sx = e ? d[ft][4] : d[ft][6];
                    float sy = e ? d[ft][5] : d[ft][7];
                    float rx = __shfl_xor_sync(0xFFFFFFFFu, sx, 1);
                    float ry = __shfl_xor_sync(0xFFFFFFFFu, sy, 1);
                    float4 v = e ? make_float4(rx, ry, d[ft][6], d[ft][7])
                                 : make_float4(d[ft][4], d[ft][5], rx, ry);
                    *reinterpret_cast<float4*>(obase + (size_t)(2 + ii) * 256 + 4 * hh) = v;
                }
            }
        }

        // One joint barrier: next-tile build STS complete AND current reads done.
        __syncthreads();
        buf ^= 1;
    }
}
}  // namespace

extern "C" void kernel_launch(void* const* d_in, const int* in_sizes, int n_in,
                              void* d_out, int out_size) {
    const int*   indp = (const int*)d_in[0];
    const int*   indn = (const int*)d_in[1];
    const float* valp = (const float*)d_in[2];
    const float* valn = (const float*)d_in[3];
    const float* wgt  = (const float*)d_in[4];
    float* out = (float*)d_out;

    cudaFuncSetAttribute(deconv_hmma_kernel,
                         cudaFuncAttributeMaxDynamicSharedMemorySize, SMEM_TOTAL);
    cudaFuncSetAttribute(deconv_hmma_kernel,
                         cudaFuncAttributePreferredSharedMemoryCarveout, 100);
    deconv_hmma_kernel<<<8 * CTAS_PER_G, THREADS, SMEM_TOTAL>>>(
        indp, indn, valp, valn, wgt, out);
}

// round 17
// speedup vs baseline: 1.5572x; 1.0400x over previous
#include <cuda_runtime.h>
#include <cuda_fp16.h>
#include <cstdint>

namespace {
constexpr int THREADS = 256;                  // 8 warps; 2 CTAs/SM => 128-reg budget
constexpr int CTAS_PER_G = 37;                // 8*37 = 296 = 2 CTAs x 148 SMs
constexpr int TILES_PER_G = 256;              // 64-position tiles (one w-row each)

// SMEM byte layout
constexpr int SM_X0  = 0;                     // X buf0: 64 pos x 64 f16 (SW128) = 8KB
constexpr int SM_X1  = 8192;                  // X buf1: 8KB
constexpr int SM_STG = 16384;                 // ind/val stage: 2 bufs x 4KB
constexpr int SM_W   = 24576;                 // W^T: 512 n x 64 f16 (SW128) = 64KB
constexpr int SMEM_TOTAL = 90112;             // -> 2 CTAs/SM (176KB + canary < 228KB)

__device__ __forceinline__ uint32_t smem_u32(const void* p) {
    uint32_t a;
    asm("{ .reg .u64 t; cvta.to.shared.u64 t, %1; cvt.u32.u64 %0, t; }" : "=r"(a) : "l"(p));
    return a;
}
__device__ __forceinline__ uint32_t sw128(uint32_t b) { return b ^ ((b >> 3) & 0x70); }

__device__ __forceinline__ void ldsm_x4(uint32_t& r0, uint32_t& r1, uint32_t& r2,
                                        uint32_t& r3, uint32_t addr) {
    asm volatile("ldmatrix.sync.aligned.m8n8.x4.shared.b16 {%0,%1,%2,%3}, [%4];"
                 : "=r"(r0), "=r"(r1), "=r"(r2), "=r"(r3) : "r"(addr));
}
__device__ __forceinline__ void mma16816(float& d0, float& d1, float& d2, float& d3,
                                         uint32_t a0, uint32_t a1, uint32_t a2, uint32_t a3,
                                         uint32_t b0, uint32_t b1) {
    asm volatile(
        "mma.sync.aligned.m16n8k16.row.col.f32.f16.f16.f32 "
        "{%0,%1,%2,%3}, {%4,%5,%6,%7}, {%8,%9}, {%0,%1,%2,%3};"
        : "+f"(d0), "+f"(d1), "+f"(d2), "+f"(d3)
        : "r"(a0), "r"(a1), "r"(a2), "r"(a3), "r"(b0), "r"(b1));
}

__global__ void __launch_bounds__(THREADS, 2)
deconv_hmma_kernel(const int* __restrict__ indp, const int* __restrict__ indn,
                   const float* __restrict__ valp, const float* __restrict__ valn,
                   const float* __restrict__ wgt, float* __restrict__ out)
{
    extern __shared__ char smc[];
    const uint32_t sb = smem_u32(smc);

    const int tid  = threadIdx.x;
    const int lane = tid & 31;
    const int wp   = tid >> 5;                 // 0..7

    const int g    = blockIdx.x / CTAS_PER_G;
    const int cidx = blockIdx.x % CTAS_PER_G;
    const int KS   = 32768;                    // k-stride in scatter tensors

    // ---- cp.async prefetch of one tile's ind/val (4 arrays x 4 k x 64 h x 4B = 4KB).
    //      256 threads x one 16B cp.async.cg each. seg = arr*4+k, lane16 covers 4 h.
    auto fetch = [&](int t, int sbuf) {
        const int bb  = t >> 6;
        const int w   = t & 63;
        const int seg = tid >> 4;              // 0..15
        const int l16 = tid & 15;
        const int arr = seg >> 2;              // 0 ip, 1 in, 2 vp, 3 vn
        const int k   = seg & 3;
        const int elem = (((bb * 32) + g) << 12) + w * 64 + k * KS + l16 * 4;
        const void* gp = (arr == 0) ? (const void*)(indp + elem)
                       : (arr == 1) ? (const void*)(indn + elem)
                       : (arr == 2) ? (const void*)(valp + elem)
                                    : (const void*)(valn + elem);
        const uint32_t sa = sb + SM_STG + sbuf * 4096 + seg * 256 + l16 * 16;
        asm volatile("cp.async.cg.shared.global [%0], [%1], 16;"
                     :: "r"(sa), "l"(gp) : "memory");
    };

    // ---- X-tile builder from staged smem (LDS, not LDG): thread h owns row h.
    auto build_x = [&](int xb, int sbuf) {
        if (tid < 64) {
            const int h = tid;
            char* xrow = smc + (xb ? SM_X1 : SM_X0) + h * 128;
            const char* sg = smc + SM_STG + sbuf * 4096;
            const uint4 z = make_uint4(0, 0, 0, 0);
            #pragma unroll
            for (int z4 = 0; z4 < 8; z4++)
                *reinterpret_cast<uint4*>(xrow + z4 * 16) = z;
            const uint32_t rsw = ((uint32_t)h & 7) << 4;
            #pragma unroll
            for (int k = 0; k < 4; k++) {      // pos scatter (k ascending)
                const int   c = *reinterpret_cast<const int*>(sg + k * 256 + h * 4);
                const float f = *reinterpret_cast<const float*>(sg + (8 + k) * 256 + h * 4);
                *reinterpret_cast<__half*>(xrow + (((uint32_t)(2 * c)) ^ rsw)) = __float2half(f);
            }
            #pragma unroll
            for (int k = 0; k < 4; k++) {      // neg scatter overwrites pos
                const int   c = *reinterpret_cast<const int*>(sg + (4 + k) * 256 + h * 4);
                const float f = *reinterpret_cast<const float*>(sg + (12 + k) * 256 + h * 4);
                *reinterpret_cast<__half*>(xrow + (((uint32_t)(2 * c)) ^ rsw)) = __float2half(f);
            }
        }
    };

    // ---- Prologue fetches (t0 and t0+37) issued before the heavy W build.
    fetch(cidx, cidx & 1);
    asm volatile("cp.async.commit_group;" ::: "memory");
    if (cidx + CTAS_PER_G < TILES_PER_G) fetch(cidx + CTAS_PER_G, (cidx + CTAS_PER_G) & 1);
    asm volatile("cp.async.commit_group;" ::: "memory");

    // ---- Build W^T in smem: Wsm[n][c] = (f16) wgt[g*32768 + c*512 + n], SW128 rows.
    for (int n = tid; n < 512; n += THREADS) {
        #pragma unroll
        for (int c8 = 0; c8 < 8; c8++) {
            const int c0 = c8 * 8;
            unsigned pk[4];
            #pragma unroll
            for (int q4 = 0; q4 < 4; q4++) {
                float f0 = __ldg(wgt + (size_t)g * 32768 + (size_t)(c0 + 2*q4    ) * 512 + n);
                float f1 = __ldg(wgt + (size_t)g * 32768 + (size_t)(c0 + 2*q4 + 1) * 512 + n);
                __half2 h = __floats2half2_rn(f0, f1);
                pk[q4] = *reinterpret_cast<unsigned*>(&h);
            }
            *reinterpret_cast<uint4*>(smc + SM_W + sw128((uint32_t)n * 128 + c0 * 2)) =
                make_uint4(pk[0], pk[1], pk[2], pk[3]);
        }
    }
    asm volatile("cp.async.wait_group 0;" ::: "memory");
    __syncthreads();                           // W + stage(t0, t0+37) visible
    build_x(0, cidx & 1);                      // first tile into X0

    // ---- B fragments for this warp's FOUR features: loaded ONCE (64 regs).
    uint32_t Bf[4][4][4];                      // [feat][k-chunk][frag]
    {
        const int nr = lane & 7;
        const int jm = lane >> 3;
        #pragma unroll
        for (int ft = 0; ft < 4; ft++) {
            const int nrow = (4 * wp + ft) * 16 + (jm >> 1) * 8 + nr;
            const int kb   = (jm & 1) * 16;
            #pragma unroll
            for (int kc = 0; kc < 4; kc++)
                ldsm_x4(Bf[ft][kc][0], Bf[ft][kc][1], Bf[ft][kc][2], Bf[ft][kc][3],
                        sb + SM_W + sw128((uint32_t)nrow * 128 + kc * 32 + kb));
        }
    }

    const int r  = lane >> 2;                  // D-frag row within m8
    const int q  = lane & 3;                   // D-frag col pair
    const int e  = q & 1;                      // 0: j={0,1} holder, 1: j={2,3}
    const int ii = q >> 1;                     // kernel row within n8 tile
    const int hh = r + 8 * e;

    int buf = 0;
    for (int t = cidx; t < TILES_PER_G; t += CTAS_PER_G) {
        // Drain the fetch issued last iteration (tile t+37), then publish everything
        // with ONE barrier: stage(t+37) visible, X(t) build visible, buffers safe.
        asm volatile("cp.async.wait_group 0;" ::: "memory");
        __syncthreads();

        const int tf = t + 2 * CTAS_PER_G;     // distance-2 prefetch
        if (tf < TILES_PER_G) fetch(tf, tf & 1);
        asm volatile("cp.async.commit_group;" ::: "memory");

        const int tn = t + CTAS_PER_G;         // build next tile from staged data
        if (tn < TILES_PER_G) build_x(buf ^ 1, tn & 1);

        const int bb = t >> 6;                 // batch
        const int w  = t & 63;                 // this tile's w-row
        const uint32_t xb = sb + (buf ? SM_X1 : SM_X0);

        #pragma unroll 1
        for (int s = 0; s < 4; s++) {
            float d[4][8];                     // [feat][tile0 0..3 | tile1 4..7]
            #pragma unroll
            for (int ft = 0; ft < 4; ft++)
                #pragma unroll
                for (int z = 0; z < 8; z++) d[ft][z] = 0.f;

            // Stream A one k-chunk at a time; exact per-kc swizzle.
            const uint32_t arow  = (uint32_t)(16 * s + (lane & 15));
            const uint32_t colb  = (uint32_t)((lane >> 4) * 16);
            const uint32_t mask  = (arow & 7u) << 4;
            const uint32_t arowb = xb + arow * 128;
            #pragma unroll
            for (int kc = 0; kc < 4; kc++) {
                uint32_t a0, a1, a2, a3;
                ldsm_x4(a0, a1, a2, a3, arowb + ((colb | (uint32_t)(kc * 32)) ^ mask));
                #pragma unroll
                for (int ft = 0; ft < 4; ft++) {
                    mma16816(d[ft][0], d[ft][1], d[ft][2], d[ft][3],
                             a0, a1, a2, a3, Bf[ft][kc][0], Bf[ft][kc][1]);
                    mma16816(d[ft][4], d[ft][5], d[ft][6], d[ft][7],
                             a0, a1, a2, a3, Bf[ft][kc][2], Bf[ft][kc][3]);
                }
            }

            const int h0 = 16 * s;
            float* ob0 = out + (((size_t)(bb * 256 + g * 32 + 4 * wp)) * 256
                                + 4 * w) * 256 + 4 * h0;

            // ---- Shuffle epilogue; streaming stores (output is write-once).
            #pragma unroll
            for (int ft = 0; ft < 4; ft++) {
                float* obase = ob0 + (size_t)ft * 65536;     // next feature: +256*256
                {   // n8 tile 0: kernel row i = ii
                    float sx = e ? d[ft][0] : d[ft][2];
                    float sy = e ? d[ft][1] : d[ft][3];
                    float rx = __shfl_xor_sync(0xFFFFFFFFu, sx, 1);
                    float ry = __shfl_xor_sync(0xFFFFFFFFu, sy, 1);
                    float4 v = e ? make_float4(rx, ry, d[ft][2], d[ft][3])
                                 : make_float4(d[ft][0], d[ft][1], rx, ry);
                    __stcs(reinterpret_cast<float4*>(obase + (size_t)ii * 256 + 4 * hh), v);
                }
                {   // n8 tile 1: kernel row i = 2 + ii
                    float sx = e ? d[ft][4] : d[ft][6];
                    float sy = e ? d[ft][5] : d[ft][7];
                    float rx = __shfl_xor_sync(0xFFFFFFFFu, sx, 1);
                    float ry = __shfl_xor_sync(0xFFFFFFFFu, sy, 1);
                    float4 v = e ? make_float4(rx, ry, d[ft][6], d[ft][7])
                                 : make_float4(d[ft][4], d[ft][5], rx, ry);
                    __stcs(reinterpret_cast<float4*>(obase + (size_t)(2 + ii) * 256 + 4 * hh), v);
                }
            }
        }
        buf ^= 1;
    }
}
}  // namespace

extern "C" void kernel_launch(void* const* d_in, const int* in_sizes, int n_in,
                              void* d_out, int out_size) {
    const int*   indp = (const int*)d_in[0];
    const int*   indn = (const int*)d_in[1];
    const float* valp = (const float*)d_in[2];
    const float* valn = (const float*)d_in[3];
    const float* wgt  = (const float*)d_in[4];
    float* out = (float*)d_out;

    cudaFuncSetAttribute(deconv_hmma_kernel,
                         cudaFuncAttributeMaxDynamicSharedMemorySize, SMEM_TOTAL);
    cudaFuncSetAttribute(deconv_hmma_kernel,
                         cudaFuncAttributePreferredSharedMemoryCarveout, 100);
    deconv_hmma_kernel<<<8 * CTAS_PER_G, THREADS, SMEM_TOTAL>>>(
        indp, indn, valp, valn, wgt, out);
}